// round 3
// baseline (speedup 1.0000x reference)
#include <cuda_runtime.h>
#include <math.h>

#define NB 16384      // batch
#define LL 200        // history length
#define CONCAT 244

// ---------------- device scratch (no allocation allowed) ----------------
__device__ float g_Wh[64 * 64];           // aW1[64:128] - aW1[128:192]
__device__ float g_Wc[64 * 64];           // aW1[0:64]  + aW1[128:192]
__device__ float g_shared[NB * CONCAT];   // per-sample concat features

// ---------------- kernel 0: fold attention weight blocks ----------------
__global__ void prep_kernel(const float* __restrict__ aW1)
{
    int i = blockIdx.x * blockDim.x + threadIdx.x;   // 0..4095 = d*64 + j
    if (i < 4096) {
        g_Wh[i] = aW1[4096 + i] - aW1[8192 + i];     // A1 - A2
        g_Wc[i] = aW1[i] + aW1[8192 + i];            // A0 + A2
    }
}

// ---------------- kernel 1: feature encode + DIN attention ----------------
// one block per sample, 256 threads
#define DIN_SMEM_FLOATS 22968

__global__ void __launch_bounds__(256) din_kernel(
    const int* __restrict__ user_id, const int* __restrict__ item_id,
    const int* __restrict__ cat_id, const int* __restrict__ dur_id,
    const float* __restrict__ user_dense, const float* __restrict__ item_dense,
    const int* __restrict__ hist,
    const float* __restrict__ user_E, const float* __restrict__ item_E,
    const float* __restrict__ cat_E, const float* __restrict__ dur_E,
    const float* __restrict__ hist_E, const float* __restrict__ Wproj,
    const float* __restrict__ aW1, const float* __restrict__ ab1,
    const float* __restrict__ aW2, const float* __restrict__ ab2,
    const float* __restrict__ aW3, const float* __restrict__ ab3)
{
    extern __shared__ float sm[];
    float* s_h    = sm;              // 12800  history 200x64
    float* s_M    = sm + 12800;      // 4096   fused 64x64
    float* s_h1   = sm + 16896;      // 4096   per-warp h1 (8 x 512)
    float* s_w2   = sm + 20992;      // 1024   aW2 64x16
    float* s_tgt  = sm + 22016;      // 64
    float* s_c    = sm + 22080;      // 64
    float* s_w3   = sm + 22144;      // 16
    float* s_b2   = sm + 22160;      // 16
    float* s_sc   = sm + 22176;      // 256
    float* s_red  = sm + 22432;      // 16
    float* s_pool = sm + 22448;      // 256
    float* s_ie   = sm + 22704;      // 64
    int*   s_seq  = (int*)(sm + 22768); // 200 ints

    const int b = blockIdx.x;
    const int tid = threadIdx.x;
    const int lane = tid & 31, w = tid >> 5;

    // ---- stage 0: load per-sample small data ----
    for (int l = tid; l < LL; l += 256) s_seq[l] = hist[b * LL + l];
    if (tid < 64) s_ie[tid] = item_E[item_id[b] * 64 + tid];
    for (int i = tid; i < 1024; i += 256) s_w2[i] = aW2[i];
    if (tid < 16) { s_w3[tid] = aW3[tid]; s_b2[tid] = ab2[tid]; }
    __syncthreads();

    // tgt = i_emb @ Wproj
    if (tid < 64) {
        float a = 0.f;
        #pragma unroll 8
        for (int d = 0; d < 64; d++) a += s_ie[d] * Wproj[d * 64 + tid];
        s_tgt[tid] = a;
    }
    __syncthreads();

    // c = tgt @ (A0+A2) + ab1 ; M = (A1-A2) + diag(tgt)*A3
    if (tid < 64) {
        float a = ab1[tid];
        #pragma unroll 8
        for (int d = 0; d < 64; d++) a += s_tgt[d] * g_Wc[d * 64 + tid];
        s_c[tid] = a;
    }
    for (int i = tid; i < 4096; i += 256) {
        int d = i >> 6;
        s_M[i] = g_Wh[i] + s_tgt[d] * aW1[12288 + i];  // A3(d,j)
    }
    // gather history embeddings (vectorized: 16 float4 per row)
    {
        float4* s_h4 = (float4*)s_h;
        for (int i = tid; i < LL * 16; i += 256) {
            int l = i >> 4, d4 = i & 15;
            s_h4[i] = ((const float4*)(hist_E + (size_t)s_seq[l] * 64))[d4];
        }
    }
    __syncthreads();

    // ---- DIN MLP: 40 chunks of 5 rows, 5 chunks per warp ----
    const float b3v = ab3[0];
    for (int c = w; c < 40; c += 8) {
        const int l0 = c * 5;
        float acc[5][2];
        #pragma unroll
        for (int i = 0; i < 5; i++) { acc[i][0] = 0.f; acc[i][1] = 0.f; }
        const float4* h4 = (const float4*)(s_h + l0 * 64);
        const float* mp = s_M + 2 * lane;
        #pragma unroll 4
        for (int d4 = 0; d4 < 16; d4++) {
            float2 m0 = *(const float2*)(mp + (d4 * 4 + 0) * 64);
            float2 m1 = *(const float2*)(mp + (d4 * 4 + 1) * 64);
            float2 m2 = *(const float2*)(mp + (d4 * 4 + 2) * 64);
            float2 m3 = *(const float2*)(mp + (d4 * 4 + 3) * 64);
            #pragma unroll
            for (int i = 0; i < 5; i++) {
                float4 hv = h4[i * 16 + d4];
                acc[i][0] += hv.x * m0.x + hv.y * m1.x + hv.z * m2.x + hv.w * m3.x;
                acc[i][1] += hv.x * m0.y + hv.y * m1.y + hv.z * m2.y + hv.w * m3.y;
            }
        }
        const float c0 = s_c[2 * lane], c1 = s_c[2 * lane + 1];
        float* h1w = s_h1 + (w << 9);
        #pragma unroll
        for (int i = 0; i < 5; i++) {
            float2 v;
            v.x = fmaxf(acc[i][0] + c0, 0.f);
            v.y = fmaxf(acc[i][1] + c1, 0.f);
            *(float2*)(h1w + i * 64 + 2 * lane) = v;
        }
        __syncwarp();
        // stage 2 (64->16 relu) + stage 3 (16->1)
        const int kk = lane & 15;
        const float w3v = s_w3[kk], b2v = s_b2[kk];
        #pragma unroll
        for (int p = 0; p < 3; p++) {
            int li = p * 2 + (lane >> 4);           // 0..5 (5 = garbage, discarded)
            float a = b2v;
            const float* hrow = h1w + (li < 5 ? li : 4) * 64;
            #pragma unroll 8
            for (int j = 0; j < 64; j++) a += hrow[j] * s_w2[j * 16 + kk];
            a = fmaxf(a, 0.f);
            float part = a * w3v;
            part += __shfl_xor_sync(0xffffffffu, part, 1);
            part += __shfl_xor_sync(0xffffffffu, part, 2);
            part += __shfl_xor_sync(0xffffffffu, part, 4);
            part += __shfl_xor_sync(0xffffffffu, part, 8);
            if (kk == 0 && li < 5) s_sc[l0 + li] = part + b3v;
        }
        __syncwarp();
    }
    __syncthreads();

    // ---- masked softmax over 200 scores ----
    for (int l = tid; l < LL; l += 256)
        if (s_seq[l] == 0) s_sc[l] = -1e9f;
    __syncthreads();
    {
        float v = (tid < LL) ? s_sc[tid] : -3.0e38f;
        #pragma unroll
        for (int o = 16; o; o >>= 1) v = fmaxf(v, __shfl_xor_sync(0xffffffffu, v, o));
        if (lane == 0) s_red[w] = v;
        __syncthreads();
        if (tid == 0) {
            float m = s_red[0];
            #pragma unroll
            for (int i = 1; i < 8; i++) m = fmaxf(m, s_red[i]);
            s_red[8] = m;
        }
        __syncthreads();
        const float mx = s_red[8];
        float e = (tid < LL) ? expf(s_sc[tid] - mx) : 0.f;
        float sv = e;
        #pragma unroll
        for (int o = 16; o; o >>= 1) sv += __shfl_xor_sync(0xffffffffu, sv, o);
        if (lane == 0) s_red[w] = sv;
        __syncthreads();
        if (tid == 0) {
            float su = 0.f;
            #pragma unroll
            for (int i = 0; i < 8; i++) su += s_red[i];
            s_red[9] = 1.f / su;
        }
        __syncthreads();
        if (tid < LL) s_sc[tid] = e * s_red[9];
    }
    __syncthreads();

    // ---- pooled = attn @ h ----
    {
        const int d = tid & 63, part = tid >> 6;
        float a = 0.f;
        for (int l = part * 50; l < part * 50 + 50; l++)
            a += s_sc[l] * s_h[l * 64 + d];
        s_pool[part * 64 + d] = a;
    }
    __syncthreads();

    // ---- write shared concat row ----
    float* orow = g_shared + b * CONCAT;
    if (tid < 64) {
        orow[64 + tid] = s_ie[tid];
        orow[180 + tid] = s_pool[tid] + s_pool[64 + tid] + s_pool[128 + tid] + s_pool[192 + tid];
    } else if (tid < 128) {
        int j = tid - 64;
        orow[j] = user_E[user_id[b] * 64 + j];
    } else if (tid < 144) {
        int j = tid - 128;
        orow[128 + j] = cat_E[cat_id[b] * 16 + j];
    } else if (tid < 152) {
        int j = tid - 144;
        orow[144 + j] = dur_E[dur_id[b] * 8 + j];
    } else if (tid < 177) {
        int j = tid - 152;
        orow[152 + j] = user_dense[b * 25 + j];
    } else if (tid < 180) {
        int j = tid - 177;
        orow[177 + j] = item_dense[b * 3 + j];
    }
}

// ---------------- kernel 2: gates + experts + towers ----------------
// 32 samples per block, 256 threads
#define MMOE_SMEM_FLOATS 26752

__global__ void __launch_bounds__(256) mmoe_kernel(
    const float* __restrict__ eW1, const float* __restrict__ eb1,
    const float* __restrict__ eW2, const float* __restrict__ eb2,
    const float* __restrict__ gW, const float* __restrict__ gb,
    const float* __restrict__ tW1, const float* __restrict__ tb1,
    const float* __restrict__ tW2, const float* __restrict__ tb2,
    const float* __restrict__ tW3, const float* __restrict__ tb3,
    float* __restrict__ out)
{
    extern __shared__ float sm[];
    float* sS  = sm;           // 32 x 244
    float* sW  = sm + 7808;    // weight panels (<=2048)
    float* sH  = sm + 9856;    // 32 x 256 hidden / tW1 / gW staging
    float* sTI = sm + 18048;   // 2 x 32 x 128 gated expert mix
    float* sG  = sm + 26240;   // 32 x 16 gates / tower consts

    const int tid = threadIdx.x;
    const int s0 = blockIdx.x * 32;

    {
        const float4* src = (const float4*)(g_shared + (size_t)s0 * CONCAT);
        float4* dst = (float4*)sS;
        for (int i = tid; i < 32 * CONCAT / 4; i += 256) dst[i] = src[i];
    }
    for (int i = tid; i < 8192; i += 256) sTI[i] = 0.f;
    // stage gate weights in smem (3904 floats) — sH is free right now
    for (int i = tid; i < 2 * CONCAT * 8; i += 256) sH[i] = gW[i];
    __syncthreads();

    // ---- gate logits then softmax over 8 experts ----
    for (int idx = tid; idx < 512; idx += 256) {
        int s = idx >> 4, te = idx & 15;
        int t = te >> 3, e = te & 7;
        float a = gb[t * 8 + e];
        const float* wp = sH + t * (CONCAT * 8) + e;
        const float* sp = sS + s * CONCAT;
        for (int k = 0; k < CONCAT; k++) a += sp[k] * wp[k * 8];
        sG[idx] = a;
    }
    __syncthreads();
    if (tid < 64) {
        float* g = sG + tid * 8;
        float m = g[0];
        #pragma unroll
        for (int e = 1; e < 8; e++) m = fmaxf(m, g[e]);
        float su = 0.f;
        #pragma unroll
        for (int e = 0; e < 8; e++) { float v = expf(g[e] - m); g[e] = v; su += v; }
        float inv = 1.f / su;
        #pragma unroll
        for (int e = 0; e < 8; e++) g[e] *= inv;
    }
    __syncthreads();

    // ---- experts ----
    for (int e = 0; e < 8; e++) {
        // stage 1: H(32x256) = relu(S @ eW1[e] + b1); thread owns hidden col tid
        float acc[32];
        {
            const float bias = eb1[e * 256 + tid];
            #pragma unroll
            for (int s = 0; s < 32; s++) acc[s] = bias;
        }
        for (int k0 = 0; k0 < CONCAT; k0 += 8) {
            const int kn = (CONCAT - k0 < 8) ? (CONCAT - k0) : 8;
            __syncthreads();
            #pragma unroll
            for (int r = 0; r < 8; r++)
                sW[r * 256 + tid] = (r < kn) ? eW1[(e * CONCAT + k0 + r) * 256 + tid] : 0.f;
            __syncthreads();
            for (int kk = 0; kk < kn; kk += 4) {
                float w0 = sW[(kk + 0) * 256 + tid];
                float w1 = sW[(kk + 1) * 256 + tid];
                float w2v = sW[(kk + 2) * 256 + tid];
                float w3v = sW[(kk + 3) * 256 + tid];
                #pragma unroll
                for (int s = 0; s < 32; s++) {
                    float4 x = *(const float4*)(sS + s * CONCAT + k0 + kk);
                    acc[s] += x.x * w0 + x.y * w1 + x.z * w2v + x.w * w3v;
                }
            }
        }
        __syncthreads();
        #pragma unroll
        for (int s = 0; s < 32; s++) sH[s * 256 + tid] = fmaxf(acc[s], 0.f);
        __syncthreads();

        // stage 2: O(32x128) = relu(H @ eW2[e] + b2)
        const int o = tid & 127, sg = tid >> 7;
        float acc2[16];
        {
            const float bias2 = eb2[e * 128 + o];
            #pragma unroll
            for (int i = 0; i < 16; i++) acc2[i] = bias2;
        }
        for (int k0 = 0; k0 < 256; k0 += 8) {
            __syncthreads();
            for (int i = tid; i < 1024; i += 256) {
                int r = i >> 7, oo = i & 127;
                sW[i] = eW2[(e * 256 + k0 + r) * 128 + oo];
            }
            __syncthreads();
            #pragma unroll
            for (int kk = 0; kk < 8; kk += 4) {
                float w0 = sW[(kk + 0) * 128 + o];
                float w1 = sW[(kk + 1) * 128 + o];
                float w2v = sW[(kk + 2) * 128 + o];
                float w3v = sW[(kk + 3) * 128 + o];
                #pragma unroll
                for (int i = 0; i < 16; i++) {
                    float4 x = *(const float4*)(sH + (sg * 16 + i) * 256 + k0 + kk);
                    acc2[i] += x.x * w0 + x.y * w1 + x.z * w2v + x.w * w3v;
                }
            }
        }
        // gate-weighted accumulation (thread owns unique (s,o) -> race free)
        #pragma unroll
        for (int i = 0; i < 16; i++) {
            float v = fmaxf(acc2[i], 0.f);
            int s = sg * 16 + i;
            sTI[s * 128 + o]        += sG[s * 16 + e] * v;
            sTI[(32 + s) * 128 + o] += sG[s * 16 + 8 + e] * v;
        }
    }

    // ---- towers ----
    for (int t = 0; t < 2; t++) {
        __syncthreads();
        for (int i = tid; i < 8192; i += 256) sH[i] = tW1[t * 8192 + i];
        for (int i = tid; i < 2048; i += 256) sW[i] = tW2[t * 2048 + i];
        if (tid < 32) sG[tid] = tW3[t * 32 + tid];
        if (tid < 64) sG[64 + tid] = tb1[t * 64 + tid];
        if (tid < 32) sG[128 + tid] = tb2[t * 32 + tid];
        if (tid == 0) sG[160] = tb3[t];
        __syncthreads();

        // x1 = relu(ti @ tW1 + tb1): 32x64
        {
            const int j = tid & 63, sg2 = tid >> 6;
            float a[8];
            #pragma unroll
            for (int i = 0; i < 8; i++) a[i] = sG[64 + j];
            const float* tiB = sTI + (t * 32 + sg2 * 8) * 128;
            for (int k = 0; k < 128; k++) {
                float wv = sH[k * 64 + j];
                #pragma unroll
                for (int i = 0; i < 8; i++) a[i] += tiB[i * 128 + k] * wv;
            }
            float* sX = sS;  // S no longer needed
            #pragma unroll
            for (int i = 0; i < 8; i++) sX[(sg2 * 8 + i) * 64 + j] = fmaxf(a[i], 0.f);
        }
        __syncthreads();
        // x2 = relu(x1 @ tW2 + tb2): 32x32
        {
            const int k2 = tid & 31, sg3 = tid >> 5;
            const float* sX = sS;
            float* sX2 = sS + 2048;   // padded stride 33
            float a[4];
            #pragma unroll
            for (int i = 0; i < 4; i++) a[i] = sG[128 + k2];
            for (int j = 0; j < 64; j++) {
                float wv = sW[j * 32 + k2];
                #pragma unroll
                for (int i = 0; i < 4; i++) a[i] += sX[(sg3 * 4 + i) * 64 + j] * wv;
            }
            #pragma unroll
            for (int i = 0; i < 4; i++) sX2[(sg3 * 4 + i) * 33 + k2] = fmaxf(a[i], 0.f);
        }
        __syncthreads();
        // logit + sigmoid
        if (tid < 32) {
            const float* sX2 = sS + 2048;
            float a = sG[160];
            #pragma unroll
            for (int k = 0; k < 32; k++) a += sX2[tid * 33 + k] * sG[k];
            out[t * NB + s0 + tid] = 1.f / (1.f + expf(-a));
        }
    }
}

// ---------------- launch ----------------
extern "C" void kernel_launch(void* const* d_in, const int* in_sizes, int n_in,
                              void* d_out, int out_size)
{
    const int*   user_id    = (const int*)d_in[0];
    const int*   item_id    = (const int*)d_in[1];
    const int*   cat_id     = (const int*)d_in[2];
    const int*   dur_id     = (const int*)d_in[3];
    const float* user_dense = (const float*)d_in[4];
    const float* item_dense = (const float*)d_in[5];
    const int*   hist       = (const int*)d_in[6];
    const float* user_E     = (const float*)d_in[7];
    const float* item_E     = (const float*)d_in[8];
    const float* cat_E      = (const float*)d_in[9];
    const float* dur_E      = (const float*)d_in[10];
    const float* hist_E     = (const float*)d_in[11];
    const float* Wproj      = (const float*)d_in[12];
    const float* aW1        = (const float*)d_in[13];
    const float* ab1        = (const float*)d_in[14];
    const float* aW2        = (const float*)d_in[15];
    const float* ab2        = (const float*)d_in[16];
    const float* aW3        = (const float*)d_in[17];
    const float* ab3        = (const float*)d_in[18];
    const float* eW1        = (const float*)d_in[19];
    const float* eb1        = (const float*)d_in[20];
    const float* eW2        = (const float*)d_in[21];
    const float* eb2        = (const float*)d_in[22];
    const float* gW         = (const float*)d_in[23];
    const float* gb         = (const float*)d_in[24];
    const float* tW1        = (const float*)d_in[25];
    const float* tb1        = (const float*)d_in[26];
    const float* tW2        = (const float*)d_in[27];
    const float* tb2        = (const float*)d_in[28];
    const float* tW3        = (const float*)d_in[29];
    const float* tb3        = (const float*)d_in[30];
    float* out = (float*)d_out;

    cudaFuncSetAttribute(din_kernel, cudaFuncAttributeMaxDynamicSharedMemorySize,
                         DIN_SMEM_FLOATS * 4);
    cudaFuncSetAttribute(mmoe_kernel, cudaFuncAttributeMaxDynamicSharedMemorySize,
                         MMOE_SMEM_FLOATS * 4);

    prep_kernel<<<16, 256>>>(aW1);
    din_kernel<<<NB, 256, DIN_SMEM_FLOATS * 4>>>(
        user_id, item_id, cat_id, dur_id, user_dense, item_dense, hist,
        user_E, item_E, cat_E, dur_E, hist_E, Wproj,
        aW1, ab1, aW2, ab2, aW3, ab3);
    mmoe_kernel<<<NB / 32, 256, MMOE_SMEM_FLOATS * 4>>>(
        eW1, eb1, eW2, eb2, gW, gb, tW1, tb1, tW2, tb2, tW3, tb3, out);
}

// round 7
// speedup vs baseline: 1.3786x; 1.3786x over previous
#include <cuda_runtime.h>
#include <math.h>

#define NB 16384      // batch
#define LL 200        // history length
#define CONCAT 244

// ---------------- device scratch (no allocation allowed) ----------------
__device__ float g_shared[NB * CONCAT];   // per-sample concat features

// ---------------- kernel 1: feature encode + DIN attention ----------------
// one block per sample, 256 threads
#define DIN_SMEM_FLOATS 22968

__global__ void __launch_bounds__(256) din_kernel(
    const int* __restrict__ user_id, const int* __restrict__ item_id,
    const int* __restrict__ cat_id, const int* __restrict__ dur_id,
    const float* __restrict__ user_dense, const float* __restrict__ item_dense,
    const int* __restrict__ hist,
    const float* __restrict__ user_E, const float* __restrict__ item_E,
    const float* __restrict__ cat_E, const float* __restrict__ dur_E,
    const float* __restrict__ hist_E, const float* __restrict__ Wproj,
    const float* __restrict__ aW1, const float* __restrict__ ab1,
    const float* __restrict__ aW2, const float* __restrict__ ab2,
    const float* __restrict__ aW3, const float* __restrict__ ab3)
{
    extern __shared__ float sm[];
    float* s_h    = sm;              // 12800  history 200x64
    float* s_M    = sm + 12800;      // 4096   fused 64x64
    float* s_h1   = sm + 16896;      // 4096   per-warp h1 (8 x 512)
    float* s_w2t  = sm + 20992;      // 1024   aW2 transposed [j4][kk][4]
    float* s_tgt  = sm + 22016;      // 64
    float* s_c    = sm + 22080;      // 64
    float* s_w3   = sm + 22144;      // 16
    float* s_b2   = sm + 22160;      // 16
    float* s_sc   = sm + 22176;      // 256
    float* s_red  = sm + 22432;      // 16
    float* s_pool = sm + 22448;      // 256
    float* s_ie   = sm + 22704;      // 64
    int*   s_seq  = (int*)(sm + 22768); // 200 ints

    const int b = blockIdx.x;
    const int tid = threadIdx.x;
    const int lane = tid & 31, w = tid >> 5;

    // ---- stage 0: load per-sample small data ----
    for (int l = tid; l < LL; l += 256) s_seq[l] = hist[b * LL + l];
    if (tid < 64) s_ie[tid] = item_E[item_id[b] * 64 + tid];
    // aW2 transpose: s_w2t[(j4*16+kk)*4+c] = aW2[(j4*4+c)*16+kk]
    for (int i = tid; i < 1024; i += 256) {
        int c = i & 3, kk = (i >> 2) & 15, j4 = i >> 6;
        s_w2t[i] = aW2[(j4 * 4 + c) * 16 + kk];
    }
    if (tid < 16) { s_w3[tid] = aW3[tid]; s_b2[tid] = ab2[tid]; }
    __syncthreads();

    // tgt = i_emb @ Wproj
    if (tid < 64) {
        float a = 0.f;
        #pragma unroll 8
        for (int d = 0; d < 64; d++) a += s_ie[d] * Wproj[d * 64 + tid];
        s_tgt[tid] = a;
    }
    __syncthreads();

    // c = tgt @ (A0+A2) + ab1 ; M = (A1-A2) + diag(tgt)*A3   (A blocks of aW1)
    if (tid < 64) {
        float a = ab1[tid];
        #pragma unroll 4
        for (int d = 0; d < 64; d++)
            a += s_tgt[d] * (aW1[d * 64 + tid] + aW1[(128 + d) * 64 + tid]);
        s_c[tid] = a;
    }
    {
        const float4* a1 = (const float4*)(aW1 + 4096);
        const float4* a2 = (const float4*)(aW1 + 8192);
        const float4* a3 = (const float4*)(aW1 + 12288);
        float4* m4 = (float4*)s_M;
        for (int i = tid; i < 1024; i += 256) {
            float tg = s_tgt[i >> 4];
            float4 x1 = a1[i], x2 = a2[i], x3 = a3[i], m;
            m.x = x1.x - x2.x + tg * x3.x;
            m.y = x1.y - x2.y + tg * x3.y;
            m.z = x1.z - x2.z + tg * x3.z;
            m.w = x1.w - x2.w + tg * x3.w;
            m4[i] = m;
        }
    }
    // gather history embeddings (vectorized: 16 float4 per row)
    {
        float4* s_h4 = (float4*)s_h;
        for (int i = tid; i < LL * 16; i += 256) {
            int l = i >> 4, d4 = i & 15;
            s_h4[i] = ((const float4*)(hist_E + (size_t)s_seq[l] * 64))[d4];
        }
    }
    __syncthreads();

    // ---- DIN MLP: 40 chunks of 5 rows, 5 chunks per warp ----
    const float b3v = ab3[0];
    for (int c = w; c < 40; c += 8) {
        const int l0 = c * 5;
        float acc[5][2];
        #pragma unroll
        for (int i = 0; i < 5; i++) { acc[i][0] = 0.f; acc[i][1] = 0.f; }
        const float4* h4 = (const float4*)(s_h + l0 * 64);
        const float* mp = s_M + 2 * lane;
        #pragma unroll 4
        for (int d4 = 0; d4 < 16; d4++) {
            float2 m0 = *(const float2*)(mp + (d4 * 4 + 0) * 64);
            float2 m1 = *(const float2*)(mp + (d4 * 4 + 1) * 64);
            float2 m2 = *(const float2*)(mp + (d4 * 4 + 2) * 64);
            float2 m3 = *(const float2*)(mp + (d4 * 4 + 3) * 64);
            #pragma unroll
            for (int i = 0; i < 5; i++) {
                float4 hv = h4[i * 16 + d4];
                acc[i][0] += hv.x * m0.x + hv.y * m1.x + hv.z * m2.x + hv.w * m3.x;
                acc[i][1] += hv.x * m0.y + hv.y * m1.y + hv.z * m2.y + hv.w * m3.y;
            }
        }
        const float c0 = s_c[2 * lane], c1 = s_c[2 * lane + 1];
        float* h1w = s_h1 + (w << 9);
        #pragma unroll
        for (int i = 0; i < 5; i++) {
            float2 v;
            v.x = fmaxf(acc[i][0] + c0, 0.f);
            v.y = fmaxf(acc[i][1] + c1, 0.f);
            *(float2*)(h1w + i * 64 + 2 * lane) = v;
        }
        __syncwarp();
        // stage 2 (64->16 relu, float4-vectorized) + stage 3 (16->1)
        const int kk = lane & 15;
        const float w3v = s_w3[kk], b2v = s_b2[kk];
        const float4* w4 = (const float4*)s_w2t;   // [(j4*16+kk)]
        #pragma unroll
        for (int p = 0; p < 3; p++) {
            int li = p * 2 + (lane >> 4);           // 0..5 (5 = garbage, discarded)
            const float4* hrow4 = (const float4*)(h1w + (li < 5 ? li : 4) * 64);
            float a = b2v;
            #pragma unroll
            for (int j4 = 0; j4 < 16; j4++) {
                float4 hv = hrow4[j4];
                float4 wv = w4[j4 * 16 + kk];
                a += hv.x * wv.x + hv.y * wv.y + hv.z * wv.z + hv.w * wv.w;
            }
            a = fmaxf(a, 0.f);
            float part = a * w3v;
            part += __shfl_xor_sync(0xffffffffu, part, 1);
            part += __shfl_xor_sync(0xffffffffu, part, 2);
            part += __shfl_xor_sync(0xffffffffu, part, 4);
            part += __shfl_xor_sync(0xffffffffu, part, 8);
            if (kk == 0 && li < 5) s_sc[l0 + li] = part + b3v;
        }
        __syncwarp();
    }
    __syncthreads();

    // ---- masked softmax over 200 scores ----
    for (int l = tid; l < LL; l += 256)
        if (s_seq[l] == 0) s_sc[l] = -1e9f;
    __syncthreads();
    {
        float v = (tid < LL) ? s_sc[tid] : -3.0e38f;
        #pragma unroll
        for (int o = 16; o; o >>= 1) v = fmaxf(v, __shfl_xor_sync(0xffffffffu, v, o));
        if (lane == 0) s_red[w] = v;
        __syncthreads();
        if (tid == 0) {
            float m = s_red[0];
            #pragma unroll
            for (int i = 1; i < 8; i++) m = fmaxf(m, s_red[i]);
            s_red[8] = m;
        }
        __syncthreads();
        const float mx = s_red[8];
        float e = (tid < LL) ? expf(s_sc[tid] - mx) : 0.f;
        float sv = e;
        #pragma unroll
        for (int o = 16; o; o >>= 1) sv += __shfl_xor_sync(0xffffffffu, sv, o);
        if (lane == 0) s_red[w] = sv;
        __syncthreads();
        if (tid == 0) {
            float su = 0.f;
            #pragma unroll
            for (int i = 0; i < 8; i++) su += s_red[i];
            s_red[9] = 1.f / su;
        }
        __syncthreads();
        if (tid < LL) s_sc[tid] = e * s_red[9];
    }
    __syncthreads();

    // ---- pooled = attn @ h ----
    {
        const int d = tid & 63, part = tid >> 6;
        float a = 0.f;
        for (int l = part * 50; l < part * 50 + 50; l++)
            a += s_sc[l] * s_h[l * 64 + d];
        s_pool[part * 64 + d] = a;
    }
    __syncthreads();

    // ---- write shared concat row ----
    float* orow = g_shared + b * CONCAT;
    if (tid < 64) {
        orow[64 + tid] = s_ie[tid];
        orow[180 + tid] = s_pool[tid] + s_pool[64 + tid] + s_pool[128 + tid] + s_pool[192 + tid];
    } else if (tid < 128) {
        int j = tid - 64;
        orow[j] = user_E[user_id[b] * 64 + j];
    } else if (tid < 144) {
        int j = tid - 128;
        orow[128 + j] = cat_E[cat_id[b] * 16 + j];
    } else if (tid < 152) {
        int j = tid - 144;
        orow[144 + j] = dur_E[dur_id[b] * 8 + j];
    } else if (tid < 177) {
        int j = tid - 152;
        orow[152 + j] = user_dense[b * 25 + j];
    } else if (tid < 180) {
        int j = tid - 177;
        orow[177 + j] = item_dense[b * 3 + j];
    }
}

// ---------------- kernel 2: gates + experts + towers ----------------
// 32 samples per block, 256 threads; expert weights streamed via LDG (L2-hot)
#define MMOE_SMEM_FLOATS 24704

__global__ void __launch_bounds__(256) mmoe_kernel(
    const float* __restrict__ eW1, const float* __restrict__ eb1,
    const float* __restrict__ eW2, const float* __restrict__ eb2,
    const float* __restrict__ gW, const float* __restrict__ gb,
    const float* __restrict__ tW1, const float* __restrict__ tb1,
    const float* __restrict__ tW2, const float* __restrict__ tb2,
    const float* __restrict__ tW3, const float* __restrict__ tb3,
    float* __restrict__ out)
{
    extern __shared__ float sm[];
    float* sS  = sm;           // 32 x 244  (towers reuse: sX @0, sX2 @2048, tW2 @4096)
    float* sH  = sm + 7808;    // 32 x 256 hidden / tW1 / gW staging
    float* sTI = sm + 16000;   // 2 x 32 x 128 gated expert mix
    float* sG  = sm + 24192;   // 32 x 16 gates / tower consts (512)

    const int tid = threadIdx.x;
    const int s0 = blockIdx.x * 32;

    {
        const float4* src = (const float4*)(g_shared + (size_t)s0 * CONCAT);
        float4* dst = (float4*)sS;
        for (int i = tid; i < 32 * CONCAT / 4; i += 256) dst[i] = src[i];
    }
    for (int i = tid; i < 8192; i += 256) sTI[i] = 0.f;
    // stage gate weights in smem (3904 floats) — sH is free right now
    for (int i = tid; i < 2 * CONCAT * 8; i += 256) sH[i] = gW[i];
    __syncthreads();

    // ---- gate logits then softmax over 8 experts ----
    for (int idx = tid; idx < 512; idx += 256) {
        int s = idx >> 4, te = idx & 15;
        int t = te >> 3, e = te & 7;
        float a = gb[t * 8 + e];
        const float* wp = sH + t * (CONCAT * 8) + e;
        const float* sp = sS + s * CONCAT;
        for (int k = 0; k < CONCAT; k++) a += sp[k] * wp[k * 8];
        sG[idx] = a;
    }
    __syncthreads();
    if (tid < 64) {
        float* g = sG + tid * 8;
        float m = g[0];
        #pragma unroll
        for (int e = 1; e < 8; e++) m = fmaxf(m, g[e]);
        float su = 0.f;
        #pragma unroll
        for (int e = 0; e < 8; e++) { float v = expf(g[e] - m); g[e] = v; su += v; }
        float inv = 1.f / su;
        #pragma unroll
        for (int e = 0; e < 8; e++) g[e] *= inv;
    }
    __syncthreads();

    // ---- experts: weights streamed from global (L2), registered prefetch ----
    for (int e = 0; e < 8; e++) {
        // stage 1: H(32x256) = relu(S @ eW1[e] + b1); thread owns hidden col = tid
        float acc[32];
        {
            const float bias = eb1[e * 256 + tid];
            #pragma unroll
            for (int s = 0; s < 32; s++) acc[s] = bias;
        }
        {
            const float* wp = eW1 + (size_t)e * CONCAT * 256 + tid;
            float w0 = wp[0], w1 = wp[256], w2v = wp[512], w3v = wp[768];
            #pragma unroll 1
            for (int q = 0; q < 60; q++) {
                const float* np = wp + (q + 1) * 1024;
                float n0 = np[0], n1 = np[256], n2 = np[512], n3 = np[768];
                const int k0 = q * 4;
                #pragma unroll
                for (int s = 0; s < 32; s++) {
                    float4 x = *(const float4*)(sS + s * CONCAT + k0);
                    acc[s] += x.x * w0 + x.y * w1 + x.z * w2v + x.w * w3v;
                }
                w0 = n0; w1 = n1; w2v = n2; w3v = n3;
            }
            #pragma unroll
            for (int s = 0; s < 32; s++) {          // last quad k=240..243
                float4 x = *(const float4*)(sS + s * CONCAT + 240);
                acc[s] += x.x * w0 + x.y * w1 + x.z * w2v + x.w * w3v;
            }
        }
        __syncthreads();   // prev expert's stage-2 readers done before overwrite
        #pragma unroll
        for (int s = 0; s < 32; s++) sH[s * 256 + tid] = fmaxf(acc[s], 0.f);
        __syncthreads();

        // stage 2: O(32x128) = relu(H @ eW2[e] + b2); thread owns (o, 16 samples)
        const int o = tid & 127, sg = tid >> 7;
        float acc2[16];
        {
            const float bias2 = eb2[e * 128 + o];
            #pragma unroll
            for (int i = 0; i < 16; i++) acc2[i] = bias2;
        }
        {
            const float* wp2 = eW2 + (size_t)e * 256 * 128 + o;
            float w0 = wp2[0], w1 = wp2[128], w2v = wp2[256], w3v = wp2[384];
            #pragma unroll 1
            for (int q = 0; q < 63; q++) {
                const float* np = wp2 + (q + 1) * 512;
                float n0 = np[0], n1 = np[128], n2 = np[256], n3 = np[384];
                const int k0 = q * 4;
                #pragma unroll
                for (int i = 0; i < 16; i++) {
                    float4 x = *(const float4*)(sH + (sg * 16 + i) * 256 + k0);
                    acc2[i] += x.x * w0 + x.y * w1 + x.z * w2v + x.w * w3v;
                }
                w0 = n0; w1 = n1; w2v = n2; w3v = n3;
            }
            #pragma unroll
            for (int i = 0; i < 16; i++) {          // last quad k=252..255
                float4 x = *(const float4*)(sH + (sg * 16 + i) * 256 + 252);
                acc2[i] += x.x * w0 + x.y * w1 + x.z * w2v + x.w * w3v;
            }
        }
        // gate-weighted accumulation (thread owns unique (s,o) -> race free)
        #pragma unroll
        for (int i = 0; i < 16; i++) {
            float v = fmaxf(acc2[i], 0.f);
            int s = sg * 16 + i;
            sTI[s * 128 + o]        += sG[s * 16 + e] * v;
            sTI[(32 + s) * 128 + o] += sG[s * 16 + 8 + e] * v;
        }
    }

    // ---- towers ----
    for (int t = 0; t < 2; t++) {
        __syncthreads();
        for (int i = tid; i < 8192; i += 256) sH[i] = tW1[t * 8192 + i];
        for (int i = tid; i < 2048; i += 256) sS[4096 + i] = tW2[t * 2048 + i];
        if (tid < 32) sG[tid] = tW3[t * 32 + tid];
        if (tid < 64) sG[64 + tid] = tb1[t * 64 + tid];
        if (tid < 32) sG[128 + tid] = tb2[t * 32 + tid];
        if (tid == 0) sG[160] = tb3[t];
        __syncthreads();

        // x1 = relu(ti @ tW1 + tb1): 32x64
        {
            const int j = tid & 63, sg2 = tid >> 6;
            float a[8];
            #pragma unroll
            for (int i = 0; i < 8; i++) a[i] = sG[64 + j];
            const float* tiB = sTI + (t * 32 + sg2 * 8) * 128;
            for (int k = 0; k < 128; k++) {
                float wv = sH[k * 64 + j];
                #pragma unroll
                for (int i = 0; i < 8; i++) a[i] += tiB[i * 128 + k] * wv;
            }
            float* sX = sS;  // S no longer needed
            #pragma unroll
            for (int i = 0; i < 8; i++) sX[(sg2 * 8 + i) * 64 + j] = fmaxf(a[i], 0.f);
        }
        __syncthreads();
        // x2 = relu(x1 @ tW2 + tb2): 32x32
        {
            const int k2 = tid & 31, sg3 = tid >> 5;
            const float* sX = sS;
            float* sX2 = sS + 2048;   // padded stride 33
            const float* w2p = sS + 4096;
            float a[4];
            #pragma unroll
            for (int i = 0; i < 4; i++) a[i] = sG[128 + k2];
            for (int j = 0; j < 64; j++) {
                float wv = w2p[j * 32 + k2];
                #pragma unroll
                for (int i = 0; i < 4; i++) a[i] += sX[(sg3 * 4 + i) * 64 + j] * wv;
            }
            #pragma unroll
            for (int i = 0; i < 4; i++) sX2[(sg3 * 4 + i) * 33 + k2] = fmaxf(a[i], 0.f);
        }
        __syncthreads();
        // logit + sigmoid
        if (tid < 32) {
            const float* sX2 = sS + 2048;
            float a = sG[160];
            #pragma unroll
            for (int k = 0; k < 32; k++) a += sX2[tid * 33 + k] * sG[k];
            out[t * NB + s0 + tid] = 1.f / (1.f + expf(-a));
        }
    }
}

// ---------------- launch ----------------
extern "C" void kernel_launch(void* const* d_in, const int* in_sizes, int n_in,
                              void* d_out, int out_size)
{
    const int*   user_id    = (const int*)d_in[0];
    const int*   item_id    = (const int*)d_in[1];
    const int*   cat_id     = (const int*)d_in[2];
    const int*   dur_id     = (const int*)d_in[3];
    const float* user_dense = (const float*)d_in[4];
    const float* item_dense = (const float*)d_in[5];
    const int*   hist       = (const int*)d_in[6];
    const float* user_E     = (const float*)d_in[7];
    const float* item_E     = (const float*)d_in[8];
    const float* cat_E      = (const float*)d_in[9];
    const float* dur_E      = (const float*)d_in[10];
    const float* hist_E     = (const float*)d_in[11];
    const float* Wproj      = (const float*)d_in[12];
    const float* aW1        = (const float*)d_in[13];
    const float* ab1        = (const float*)d_in[14];
    const float* aW2        = (const float*)d_in[15];
    const float* ab2        = (const float*)d_in[16];
    const float* aW3        = (const float*)d_in[17];
    const float* ab3        = (const float*)d_in[18];
    const float* eW1        = (const float*)d_in[19];
    const float* eb1        = (const float*)d_in[20];
    const float* eW2        = (const float*)d_in[21];
    const float* eb2        = (const float*)d_in[22];
    const float* gW         = (const float*)d_in[23];
    const float* gb         = (const float*)d_in[24];
    const float* tW1        = (const float*)d_in[25];
    const float* tb1        = (const float*)d_in[26];
    const float* tW2        = (const float*)d_in[27];
    const float* tb2        = (const float*)d_in[28];
    const float* tW3        = (const float*)d_in[29];
    const float* tb3        = (const float*)d_in[30];
    float* out = (float*)d_out;

    cudaFuncSetAttribute(din_kernel, cudaFuncAttributeMaxDynamicSharedMemorySize,
                         DIN_SMEM_FLOATS * 4);
    cudaFuncSetAttribute(mmoe_kernel, cudaFuncAttributeMaxDynamicSharedMemorySize,
                         MMOE_SMEM_FLOATS * 4);

    din_kernel<<<NB, 256, DIN_SMEM_FLOATS * 4>>>(
        user_id, item_id, cat_id, dur_id, user_dense, item_dense, hist,
        user_E, item_E, cat_E, dur_E, hist_E, Wproj,
        aW1, ab1, aW2, ab2, aW3, ab3);
    mmoe_kernel<<<NB / 32, 256, MMOE_SMEM_FLOATS * 4>>>(
        eW1, eb1, eW2, eb2, gW, gb, tW1, tb1, tW2, tb2, tW3, tb3, out);
}